// round 4
// baseline (speedup 1.0000x reference)
#include <cuda_runtime.h>

#define NN_MAX 100000
#define CH 64
#define TILE_E 16
#define WARPS 8
#define NBLK 1184
#define WEA 36

__device__ float g_PQ[(size_t)NN_MAX * 128];
__device__ int g_is64;

__device__ __forceinline__ unsigned f2tf32(float f) {
    unsigned u;
    asm("cvt.rna.tf32.f32 %0, %1;" : "=r"(u) : "f"(f));
    return u;
}

__device__ __forceinline__ void mma_tf32(float c[4], unsigned a0, unsigned a1,
                                         unsigned a2, unsigned a3,
                                         unsigned b0, unsigned b1) {
    asm volatile(
        "mma.sync.aligned.m16n8k8.row.col.f32.tf32.tf32.f32 "
        "{%0,%1,%2,%3}, {%4,%5,%6,%7}, {%8,%9}, {%0,%1,%2,%3};"
        : "+f"(c[0]), "+f"(c[1]), "+f"(c[2]), "+f"(c[3])
        : "r"(a0), "r"(a1), "r"(a2), "r"(a3), "r"(b0), "r"(b1));
}

// ---------------------------------------------------------------------------
__global__ void detect_kernel(const unsigned* __restrict__ ei_raw) {
    int t = threadIdx.x;
    unsigned nz = ei_raw[2 * t + 1] | ei_raw[2 * (t + 32) + 1];
    unsigned b = __ballot_sync(0xFFFFFFFFu, nz != 0u);
    if (t == 0) g_is64 = (b == 0u);
}

__global__ void zero_kernel(float4* __restrict__ out, int n4) {
    int i = blockIdx.x * blockDim.x + threadIdx.x;
    if (i < n4) out[i] = make_float4(0.f, 0.f, 0.f, 0.f);
}

// ---------------------------------------------------------------------------
// Node precompute with SWIZZLED store layout:
// within each 64-float half, lane-fragment (t', q) [cols 8t'+2q, +1] is stored
// at float offset (it*4+q)*4 + w*2  where it = t'>>1, w = t'&1.
// => edge kernel reads each lane's data as 4 contiguous float4s.
// ---------------------------------------------------------------------------
__global__ __launch_bounds__(256) void node_precompute(
    const float* __restrict__ x, const float* __restrict__ W1, int n_nodes) {
    __shared__ uint2 sBp[8 * 16 * 32];

    for (int idx = threadIdx.x; idx < 8 * 16 * 32; idx += 256) {
        int lane = idx & 31, tt = (idx >> 5) & 15, s = idx >> 9;
        int gr = lane >> 2, q = lane & 3;
        int n = 8 * tt + gr;
        int k0 = 8 * s + q, k1 = k0 + 4;
        float w0 = (n < 64) ? W1[(size_t)k0 * CH + n] : W1[(size_t)(64 + k0) * CH + n - 64];
        float w1 = (n < 64) ? W1[(size_t)k1 * CH + n] : W1[(size_t)(64 + k1) * CH + n - 64];
        sBp[idx] = make_uint2(f2tf32(w0), f2tf32(w1));
    }
    __syncthreads();

    const int warp = threadIdx.x >> 5, lane = threadIdx.x & 31;
    const int gr = lane >> 2, q = lane & 3;
    const int tile = blockIdx.x * 8 + warp;
    const int base = tile * 16;
    if (base >= n_nodes) return;
    const int r0 = base + gr, r1 = base + gr + 8;
    const bool v0 = r0 < n_nodes, v1 = r1 < n_nodes;

    float h[16][4];
#pragma unroll
    for (int t = 0; t < 16; t++)
        h[t][0] = h[t][1] = h[t][2] = h[t][3] = 0.f;

#pragma unroll
    for (int s = 0; s < 8; s++) {
        unsigned a0 = 0, a1 = 0, a2 = 0, a3 = 0;
        if (v0) {
            const float* r = x + (size_t)r0 * CH + 8 * s;
            a0 = f2tf32(r[q]); a2 = f2tf32(r[q + 4]);
        }
        if (v1) {
            const float* r = x + (size_t)r1 * CH + 8 * s;
            a1 = f2tf32(r[q]); a3 = f2tf32(r[q + 4]);
        }
#pragma unroll
        for (int t = 0; t < 16; t++) {
            uint2 b = sBp[(s * 16 + t) * 32 + lane];
            mma_tf32(h[t], a0, a1, a2, a3, b.x, b.y);
        }
    }

#pragma unroll
    for (int t = 0; t < 16; t++) {
        int tp = t & 7, half = t >> 3;
        int it = tp >> 1, w = tp & 1;
        int off = half * 64 + (it * 4 + q) * 4 + w * 2;
        if (v0) *(float2*)&g_PQ[(size_t)r0 * 128 + off] = make_float2(h[t][0], h[t][1]);
        if (v1) *(float2*)&g_PQ[(size_t)r1 * 128 + off] = make_float2(h[t][2], h[t][3]);
    }
}

// ---------------------------------------------------------------------------
// Edge kernel: warp = 16 edges; W2 fragments register-resident; PQ gather via
// swizzled float4; W1c via LDS.128.
// ---------------------------------------------------------------------------
__global__ __launch_bounds__(256, 1) void edge_kernel(
    const void* __restrict__ ei, const float* __restrict__ ea,
    const float* __restrict__ W1, const float* __restrict__ b1,
    const float* __restrict__ gamma, const float* __restrict__ beta,
    const float* __restrict__ W2, const float* __restrict__ b2,
    float* __restrict__ out, int n_edges) {
    __shared__ uint4 sW1q[4 * 4 * 32];        // 8 KB  (s, tpair, lane)
    __shared__ float sea[WARPS][16 * WEA];    // 18 KB
    __shared__ float sb1[CH], sb2[CH], sgm[CH], sbt[CH];

    const int warp = threadIdx.x >> 5, lane = threadIdx.x & 31;
    const int gr = lane >> 2;
    const int q  = lane & 3;

    for (int idx = threadIdx.x; idx < 4 * 4 * 32; idx += 256) {
        int l = idx & 31, tp = (idx >> 5) & 3, s = idx >> 7;
        int g2 = l >> 2, q2 = l & 3;
        int n0 = 8 * (2 * tp) + g2, n1 = 8 * (2 * tp + 1) + g2;
        int k0 = 8 * s + q2, k1 = k0 + 4;
        sW1q[idx] = make_uint4(f2tf32(W1[(size_t)(128 + k0) * CH + n0]),
                               f2tf32(W1[(size_t)(128 + k1) * CH + n0]),
                               f2tf32(W1[(size_t)(128 + k0) * CH + n1]),
                               f2tf32(W1[(size_t)(128 + k1) * CH + n1]));
    }
    if (threadIdx.x < CH) {
        sb1[threadIdx.x] = b1[threadIdx.x];
        sb2[threadIdx.x] = b2[threadIdx.x];
        sgm[threadIdx.x] = gamma[threadIdx.x];
        sbt[threadIdx.x] = beta[threadIdx.x];
    }
    __syncthreads();

    // ---- W2 fragments: register-resident, loop-invariant ----
    unsigned w2r[8][8][2];
#pragma unroll
    for (int s = 0; s < 8; s++)
#pragma unroll
        for (int t = 0; t < 8; t++) {
            w2r[s][t][0] = f2tf32(__ldg(&W2[(size_t)(8 * s + q) * CH + 8 * t + gr]));
            w2r[s][t][1] = f2tf32(__ldg(&W2[(size_t)(8 * s + q + 4) * CH + 8 * t + gr]));
        }

    const int is64 = g_is64;
    const unsigned FULL = 0xFFFFFFFFu;
    const int n_tiles = (n_edges + TILE_E - 1) / TILE_E;
    float* mea = sea[warp];

    for (int tile = blockIdx.x * WARPS + warp; tile < n_tiles;
         tile += gridDim.x * WARPS) {
        const int base = tile * TILE_E;

        // ---- edge indices ----
        int v = 0;
        {
            int e = base + (lane & 15);
            if (e < n_edges) {
                if (is64) {
                    const long long* p = (const long long*)ei;
                    v = (int)((lane < 16) ? p[e] : p[(size_t)n_edges + e]);
                } else {
                    const int* p = (const int*)ei;
                    v = (lane < 16) ? p[e] : p[(size_t)n_edges + e];
                }
            }
        }
        const int r0 = gr, r1 = gr + 8;
        const int i0 = __shfl_sync(FULL, v, r0), j0 = __shfl_sync(FULL, v, 16 + r0);
        const int i1 = __shfl_sync(FULL, v, r1), j1 = __shfl_sync(FULL, v, 16 + r1);
        const bool v0 = (base + r0) < n_edges, v1 = (base + r1) < n_edges;

        // ---- stage ea tile to smem ----
        __syncwarp();
        {
            const float* src = ea + (size_t)base * 32;
#pragma unroll
            for (int it = 0; it < 4; it++) {
                int idx = lane + 32 * it;
                int row = idx >> 3, c4 = idx & 7;
                float4 val = make_float4(0.f, 0.f, 0.f, 0.f);
                if (base + row < n_edges) val = *(const float4*)(src + row * 32 + c4 * 4);
                *(float4*)&mea[row * WEA + c4 * 4] = val;
            }
        }
        __syncwarp();

        // ---- GEMM1: h = ea @ W1c ----
        float h[8][4];
#pragma unroll
        for (int t = 0; t < 8; t++)
            h[t][0] = h[t][1] = h[t][2] = h[t][3] = 0.f;

#pragma unroll
        for (int s = 0; s < 4; s++) {
            unsigned a0 = f2tf32(mea[r0 * WEA + 8 * s + q]);
            unsigned a2 = f2tf32(mea[r0 * WEA + 8 * s + q + 4]);
            unsigned a1 = f2tf32(mea[r1 * WEA + 8 * s + q]);
            unsigned a3 = f2tf32(mea[r1 * WEA + 8 * s + q + 4]);
#pragma unroll
            for (int tp = 0; tp < 4; tp++) {
                uint4 b = sW1q[(s * 4 + tp) * 32 + lane];
                mma_tf32(h[2 * tp],     a0, a1, a2, a3, b.x, b.y);
                mma_tf32(h[2 * tp + 1], a0, a1, a2, a3, b.z, b.w);
            }
        }

        // ---- PQ gather (swizzled layout: 16 LDG.128, 1 line per gr each) ----
        {
            const float* Pi0 = g_PQ + (size_t)i0 * 128;
            const float* Qj0 = g_PQ + (size_t)j0 * 128 + 64;
            const float* Pi1 = g_PQ + (size_t)i1 * 128;
            const float* Qj1 = g_PQ + (size_t)j1 * 128 + 64;
#pragma unroll
            for (int it = 0; it < 4; it++) {
                int off = (it * 4 + q) * 4;
                float4 pa = *(const float4*)&Pi0[off];
                float4 qa = *(const float4*)&Qj0[off];
                float4 pb = *(const float4*)&Pi1[off];
                float4 qb = *(const float4*)&Qj1[off];
                int t0 = 2 * it, t1 = 2 * it + 1;
                int c0 = 8 * t0 + 2 * q, c1 = 8 * t1 + 2 * q;
                h[t0][0] += pa.x + qa.x + sb1[c0];
                h[t0][1] += pa.y + qa.y + sb1[c0 + 1];
                h[t1][0] += pa.z + qa.z + sb1[c1];
                h[t1][1] += pa.w + qa.w + sb1[c1 + 1];
                h[t0][2] += pb.x + qb.x + sb1[c0];
                h[t0][3] += pb.y + qb.y + sb1[c0 + 1];
                h[t1][2] += pb.z + qb.z + sb1[c1];
                h[t1][3] += pb.w + qb.w + sb1[c1 + 1];
            }
        }

        // ---- LayerNorm ----
        float s0 = 0, ss0 = 0, s1 = 0, ss1 = 0;
#pragma unroll
        for (int t = 0; t < 8; t++) {
            s0 += h[t][0] + h[t][1]; ss0 += h[t][0] * h[t][0] + h[t][1] * h[t][1];
            s1 += h[t][2] + h[t][3]; ss1 += h[t][2] * h[t][2] + h[t][3] * h[t][3];
        }
#pragma unroll
        for (int o = 1; o <= 2; o <<= 1) {
            s0 += __shfl_xor_sync(FULL, s0, o); ss0 += __shfl_xor_sync(FULL, ss0, o);
            s1 += __shfl_xor_sync(FULL, s1, o); ss1 += __shfl_xor_sync(FULL, ss1, o);
        }
        float mu0 = s0 * (1.f / 64.f), rs0 = rsqrtf(ss0 * (1.f / 64.f) - mu0 * mu0 + 1e-5f);
        float mu1 = s1 * (1.f / 64.f), rs1 = rsqrtf(ss1 * (1.f / 64.f) - mu1 * mu1 + 1e-5f);

        // ---- gamma/beta + exact GELU ----
#pragma unroll
        for (int t = 0; t < 8; t++) {
            int c = 8 * t + 2 * q;
            float g00 = (h[t][0] - mu0) * rs0 * sgm[c]     + sbt[c];
            float g01 = (h[t][1] - mu0) * rs0 * sgm[c + 1] + sbt[c + 1];
            float g10 = (h[t][2] - mu1) * rs1 * sgm[c]     + sbt[c];
            float g11 = (h[t][3] - mu1) * rs1 * sgm[c + 1] + sbt[c + 1];
            h[t][0] = 0.5f * g00 * (1.f + erff(g00 * 0.7071067811865476f));
            h[t][1] = 0.5f * g01 * (1.f + erff(g01 * 0.7071067811865476f));
            h[t][2] = 0.5f * g10 * (1.f + erff(g10 * 0.7071067811865476f));
            h[t][3] = 0.5f * g11 * (1.f + erff(g11 * 0.7071067811865476f));
        }

        // ---- GEMM2 with register-resident W2 ----
        float m[8][4];
#pragma unroll
        for (int t = 0; t < 8; t++)
            m[t][0] = m[t][1] = m[t][2] = m[t][3] = 0.f;

        const int srcA = (lane & ~3) | (q >> 1);
        const int srcB = srcA + 2;
#pragma unroll
        for (int s = 0; s < 8; s++) {
            float t00 = __shfl_sync(FULL, h[s][0], srcA);
            float t01 = __shfl_sync(FULL, h[s][1], srcA);
            float t10 = __shfl_sync(FULL, h[s][2], srcA);
            float t11 = __shfl_sync(FULL, h[s][3], srcA);
            float u00 = __shfl_sync(FULL, h[s][0], srcB);
            float u01 = __shfl_sync(FULL, h[s][1], srcB);
            float u10 = __shfl_sync(FULL, h[s][2], srcB);
            float u11 = __shfl_sync(FULL, h[s][3], srcB);
            unsigned a0 = f2tf32((q & 1) ? t01 : t00);
            unsigned a1 = f2tf32((q & 1) ? t11 : t10);
            unsigned a2 = f2tf32((q & 1) ? u01 : u00);
            unsigned a3 = f2tf32((q & 1) ? u11 : u10);
#pragma unroll
            for (int t = 0; t < 8; t++)
                mma_tf32(m[t], a0, a1, a2, a3, w2r[s][t][0], w2r[s][t][1]);
        }

        // ---- v4 scatter-add ----
#pragma unroll
        for (int t = 0; t < 8; t++) {
            int c = 8 * t + 2 * q;
            float p0 = m[t][0] + sb2[c], p1 = m[t][1] + sb2[c + 1];
            float e0 = __shfl_xor_sync(FULL, p0, 1);
            float e1 = __shfl_xor_sync(FULL, p1, 1);
            float q2 = m[t][2] + sb2[c], q3 = m[t][3] + sb2[c + 1];
            float e2 = __shfl_xor_sync(FULL, q2, 1);
            float e3 = __shfl_xor_sync(FULL, q3, 1);
            if ((q & 1) == 0) {
                if (v0) {
                    float* dst = out + (size_t)j0 * CH + 8 * t + 2 * q;
                    asm volatile("red.global.add.v4.f32 [%0], {%1,%2,%3,%4};"
                                 :: "l"(dst), "f"(p0), "f"(p1), "f"(e0), "f"(e1)
                                 : "memory");
                }
            } else {
                if (v1) {
                    float* dst = out + (size_t)j1 * CH + 8 * t + 2 * (q - 1);
                    asm volatile("red.global.add.v4.f32 [%0], {%1,%2,%3,%4};"
                                 :: "l"(dst), "f"(e2), "f"(e3), "f"(q2), "f"(q3)
                                 : "memory");
                }
            }
        }
    }
}

// ---------------------------------------------------------------------------
extern "C" void kernel_launch(void* const* d_in, const int* in_sizes, int n_in,
                              void* d_out, int out_size) {
    const float* x     = (const float*)d_in[0];
    const void*  ei    = d_in[1];
    const float* ea    = (const float*)d_in[2];
    const float* W1    = (const float*)d_in[3];
    const float* b1    = (const float*)d_in[4];
    const float* gamma = (const float*)d_in[5];
    const float* beta  = (const float*)d_in[6];
    const float* W2    = (const float*)d_in[7];
    const float* b2    = (const float*)d_in[8];
    float* out = (float*)d_out;

    int n_nodes = in_sizes[0] / CH;
    int n_edges = in_sizes[2] / 32;

    detect_kernel<<<1, 32>>>((const unsigned*)ei);

    int n4 = out_size / 4;
    zero_kernel<<<(n4 + 255) / 256, 256>>>((float4*)out, n4);

    int n_node_tiles = (n_nodes + 15) / 16;
    node_precompute<<<(n_node_tiles + 7) / 8, 256>>>(x, W1, n_nodes);

    edge_kernel<<<NBLK, 256>>>(ei, ea, W1, b1, gamma, beta, W2, b2, out, n_edges);
}

// round 6
// speedup vs baseline: 1.3629x; 1.3629x over previous
#include <cuda_runtime.h>

#define NN_MAX 100000
#define CH 64
#define TILE_E 16
#define WARPS 8
#define NBLK 1184
#define WEA 36

__device__ float g_PQ[(size_t)NN_MAX * 128];
__device__ int g_is64;

__device__ __forceinline__ unsigned f2tf32(float f) {
    unsigned u;
    asm("cvt.rna.tf32.f32 %0, %1;" : "=r"(u) : "f"(f));
    return u;
}

__device__ __forceinline__ void mma_tf32(float c[4], unsigned a0, unsigned a1,
                                         unsigned a2, unsigned a3,
                                         unsigned b0, unsigned b1) {
    asm volatile(
        "mma.sync.aligned.m16n8k8.row.col.f32.tf32.tf32.f32 "
        "{%0,%1,%2,%3}, {%4,%5,%6,%7}, {%8,%9}, {%0,%1,%2,%3};"
        : "+f"(c[0]), "+f"(c[1]), "+f"(c[2]), "+f"(c[3])
        : "r"(a0), "r"(a1), "r"(a2), "r"(a3), "r"(b0), "r"(b1));
}

// ---------------------------------------------------------------------------
__global__ void detect_kernel(const unsigned* __restrict__ ei_raw) {
    int t = threadIdx.x;
    unsigned nz = ei_raw[2 * t + 1] | ei_raw[2 * (t + 32) + 1];
    unsigned b = __ballot_sync(0xFFFFFFFFu, nz != 0u);
    if (t == 0) g_is64 = (b == 0u);
}

__global__ void zero_kernel(float4* __restrict__ out, int n4) {
    int i = blockIdx.x * blockDim.x + threadIdx.x;
    if (i < n4) out[i] = make_float4(0.f, 0.f, 0.f, 0.f);
}

// ---------------------------------------------------------------------------
// Node precompute with SWIZZLED store layout (see edge kernel PQ gather).
// ---------------------------------------------------------------------------
__global__ __launch_bounds__(256) void node_precompute(
    const float* __restrict__ x, const float* __restrict__ W1, int n_nodes) {
    __shared__ uint2 sBp[8 * 16 * 32];

    for (int idx = threadIdx.x; idx < 8 * 16 * 32; idx += 256) {
        int lane = idx & 31, tt = (idx >> 5) & 15, s = idx >> 9;
        int gr = lane >> 2, q = lane & 3;
        int n = 8 * tt + gr;
        int k0 = 8 * s + q, k1 = k0 + 4;
        float w0 = (n < 64) ? W1[(size_t)k0 * CH + n] : W1[(size_t)(64 + k0) * CH + n - 64];
        float w1 = (n < 64) ? W1[(size_t)k1 * CH + n] : W1[(size_t)(64 + k1) * CH + n - 64];
        sBp[idx] = make_uint2(f2tf32(w0), f2tf32(w1));
    }
    __syncthreads();

    const int warp = threadIdx.x >> 5, lane = threadIdx.x & 31;
    const int gr = lane >> 2, q = lane & 3;
    const int tile = blockIdx.x * 8 + warp;
    const int base = tile * 16;
    if (base >= n_nodes) return;
    const int r0 = base + gr, r1 = base + gr + 8;
    const bool v0 = r0 < n_nodes, v1 = r1 < n_nodes;

    float h[16][4];
#pragma unroll
    for (int t = 0; t < 16; t++)
        h[t][0] = h[t][1] = h[t][2] = h[t][3] = 0.f;

#pragma unroll
    for (int s = 0; s < 8; s++) {
        unsigned a0 = 0, a1 = 0, a2 = 0, a3 = 0;
        if (v0) {
            const float* r = x + (size_t)r0 * CH + 8 * s;
            a0 = f2tf32(r[q]); a2 = f2tf32(r[q + 4]);
        }
        if (v1) {
            const float* r = x + (size_t)r1 * CH + 8 * s;
            a1 = f2tf32(r[q]); a3 = f2tf32(r[q + 4]);
        }
#pragma unroll
        for (int t = 0; t < 16; t++) {
            uint2 b = sBp[(s * 16 + t) * 32 + lane];
            mma_tf32(h[t], a0, a1, a2, a3, b.x, b.y);
        }
    }

#pragma unroll
    for (int t = 0; t < 16; t++) {
        int tp = t & 7, half = t >> 3;
        int it = tp >> 1, w = tp & 1;
        int off = half * 64 + (it * 4 + q) * 4 + w * 2;
        if (v0) *(float2*)&g_PQ[(size_t)r0 * 128 + off] = make_float2(h[t][0], h[t][1]);
        if (v1) *(float2*)&g_PQ[(size_t)r1 * 128 + off] = make_float2(h[t][2], h[t][3]);
    }
}

// ---------------------------------------------------------------------------
// Edge kernel: warp = 16 edges; W1c and W2 as uint4 smem (LDS.128);
// PQ gather via swizzled float4 (LDG.128, single line per gr).
// ---------------------------------------------------------------------------
__global__ __launch_bounds__(256, 2) void edge_kernel(
    const void* __restrict__ ei, const float* __restrict__ ea,
    const float* __restrict__ W1, const float* __restrict__ b1,
    const float* __restrict__ gamma, const float* __restrict__ beta,
    const float* __restrict__ W2, const float* __restrict__ b2,
    float* __restrict__ out, int n_edges) {
    __shared__ uint4 sW1q[4 * 4 * 32];        //  8 KB (s, tpair, lane)
    __shared__ uint4 sW2q[8 * 4 * 32];        // 16 KB (s, tpair, lane)
    __shared__ float sea[WARPS][16 * WEA];    // 18 KB
    __shared__ float sb1[CH], sb2[CH], sgm[CH], sbt[CH];

    for (int idx = threadIdx.x; idx < 4 * 4 * 32; idx += 256) {
        int l = idx & 31, tp = (idx >> 5) & 3, s = idx >> 7;
        int g2 = l >> 2, q2 = l & 3;
        int n0 = 8 * (2 * tp) + g2, n1 = 8 * (2 * tp + 1) + g2;
        int k0 = 8 * s + q2, k1 = k0 + 4;
        sW1q[idx] = make_uint4(f2tf32(W1[(size_t)(128 + k0) * CH + n0]),
                               f2tf32(W1[(size_t)(128 + k1) * CH + n0]),
                               f2tf32(W1[(size_t)(128 + k0) * CH + n1]),
                               f2tf32(W1[(size_t)(128 + k1) * CH + n1]));
    }
    for (int idx = threadIdx.x; idx < 8 * 4 * 32; idx += 256) {
        int l = idx & 31, tp = (idx >> 5) & 3, s = idx >> 7;
        int g2 = l >> 2, q2 = l & 3;
        int n0 = 8 * (2 * tp) + g2, n1 = 8 * (2 * tp + 1) + g2;
        int k0 = 8 * s + q2, k1 = k0 + 4;
        sW2q[idx] = make_uint4(f2tf32(W2[(size_t)k0 * CH + n0]),
                               f2tf32(W2[(size_t)k1 * CH + n0]),
                               f2tf32(W2[(size_t)k0 * CH + n1]),
                               f2tf32(W2[(size_t)k1 * CH + n1]));
    }
    if (threadIdx.x < CH) {
        sb1[threadIdx.x] = b1[threadIdx.x];
        sb2[threadIdx.x] = b2[threadIdx.x];
        sgm[threadIdx.x] = gamma[threadIdx.x];
        sbt[threadIdx.x] = beta[threadIdx.x];
    }
    __syncthreads();

    const int warp = threadIdx.x >> 5, lane = threadIdx.x & 31;
    const int gr = lane >> 2;
    const int q  = lane & 3;
    const int is64 = g_is64;
    const unsigned FULL = 0xFFFFFFFFu;
    const int n_tiles = (n_edges + TILE_E - 1) / TILE_E;
    float* mea = sea[warp];

    for (int tile = blockIdx.x * WARPS + warp; tile < n_tiles;
         tile += gridDim.x * WARPS) {
        const int base = tile * TILE_E;

        // ---- edge indices ----
        int v = 0;
        {
            int e = base + (lane & 15);
            if (e < n_edges) {
                if (is64) {
                    const long long* p = (const long long*)ei;
                    v = (int)((lane < 16) ? p[e] : p[(size_t)n_edges + e]);
                } else {
                    const int* p = (const int*)ei;
                    v = (lane < 16) ? p[e] : p[(size_t)n_edges + e];
                }
            }
        }
        const int r0 = gr, r1 = gr + 8;
        const int i0 = __shfl_sync(FULL, v, r0), j0 = __shfl_sync(FULL, v, 16 + r0);
        const int i1 = __shfl_sync(FULL, v, r1), j1 = __shfl_sync(FULL, v, 16 + r1);
        const bool v0 = (base + r0) < n_edges, v1 = (base + r1) < n_edges;

        // ---- stage ea tile to smem ----
        __syncwarp();
        {
            const float* src = ea + (size_t)base * 32;
#pragma unroll
            for (int it = 0; it < 4; it++) {
                int idx = lane + 32 * it;
                int row = idx >> 3, c4 = idx & 7;
                float4 val = make_float4(0.f, 0.f, 0.f, 0.f);
                if (base + row < n_edges) val = *(const float4*)(src + row * 32 + c4 * 4);
                *(float4*)&mea[row * WEA + c4 * 4] = val;
            }
        }
        __syncwarp();

        // ---- GEMM1: h = ea @ W1c ----
        float h[8][4];
#pragma unroll
        for (int t = 0; t < 8; t++)
            h[t][0] = h[t][1] = h[t][2] = h[t][3] = 0.f;

#pragma unroll
        for (int s = 0; s < 4; s++) {
            unsigned a0 = f2tf32(mea[r0 * WEA + 8 * s + q]);
            unsigned a2 = f2tf32(mea[r0 * WEA + 8 * s + q + 4]);
            unsigned a1 = f2tf32(mea[r1 * WEA + 8 * s + q]);
            unsigned a3 = f2tf32(mea[r1 * WEA + 8 * s + q + 4]);
#pragma unroll
            for (int tp = 0; tp < 4; tp++) {
                uint4 b = sW1q[(s * 4 + tp) * 32 + lane];
                mma_tf32(h[2 * tp],     a0, a1, a2, a3, b.x, b.y);
                mma_tf32(h[2 * tp + 1], a0, a1, a2, a3, b.z, b.w);
            }
        }

        // ---- PQ gather (swizzled layout: 16 LDG.128, 1 line per gr each) ----
        {
            const float* Pi0 = g_PQ + (size_t)i0 * 128;
            const float* Qj0 = g_PQ + (size_t)j0 * 128 + 64;
            const float* Pi1 = g_PQ + (size_t)i1 * 128;
            const float* Qj1 = g_PQ + (size_t)j1 * 128 + 64;
#pragma unroll
            for (int it = 0; it < 4; it++) {
                int off = (it * 4 + q) * 4;
                float4 pa = *(const float4*)&Pi0[off];
                float4 qa = *(const float4*)&Qj0[off];
                float4 pb = *(const float4*)&Pi1[off];
                float4 qb = *(const float4*)&Qj1[off];
                int t0 = 2 * it, t1 = 2 * it + 1;
                int c0 = 8 * t0 + 2 * q, c1 = 8 * t1 + 2 * q;
                h[t0][0] += pa.x + qa.x + sb1[c0];
                h[t0][1] += pa.y + qa.y + sb1[c0 + 1];
                h[t1][0] += pa.z + qa.z + sb1[c1];
                h[t1][1] += pa.w + qa.w + sb1[c1 + 1];
                h[t0][2] += pb.x + qb.x + sb1[c0];
                h[t0][3] += pb.y + qb.y + sb1[c0 + 1];
                h[t1][2] += pb.z + qb.z + sb1[c1];
                h[t1][3] += pb.w + qb.w + sb1[c1 + 1];
            }
        }

        // ---- LayerNorm ----
        float s0 = 0, ss0 = 0, s1 = 0, ss1 = 0;
#pragma unroll
        for (int t = 0; t < 8; t++) {
            s0 += h[t][0] + h[t][1]; ss0 += h[t][0] * h[t][0] + h[t][1] * h[t][1];
            s1 += h[t][2] + h[t][3]; ss1 += h[t][2] * h[t][2] + h[t][3] * h[t][3];
        }
#pragma unroll
        for (int o = 1; o <= 2; o <<= 1) {
            s0 += __shfl_xor_sync(FULL, s0, o); ss0 += __shfl_xor_sync(FULL, ss0, o);
            s1 += __shfl_xor_sync(FULL, s1, o); ss1 += __shfl_xor_sync(FULL, ss1, o);
        }
        float mu0 = s0 * (1.f / 64.f), rs0 = rsqrtf(ss0 * (1.f / 64.f) - mu0 * mu0 + 1e-5f);
        float mu1 = s1 * (1.f / 64.f), rs1 = rsqrtf(ss1 * (1.f / 64.f) - mu1 * mu1 + 1e-5f);

        // ---- gamma/beta + exact GELU ----
#pragma unroll
        for (int t = 0; t < 8; t++) {
            int c = 8 * t + 2 * q;
            float g00 = (h[t][0] - mu0) * rs0 * sgm[c]     + sbt[c];
            float g01 = (h[t][1] - mu0) * rs0 * sgm[c + 1] + sbt[c + 1];
            float g10 = (h[t][2] - mu1) * rs1 * sgm[c]     + sbt[c];
            float g11 = (h[t][3] - mu1) * rs1 * sgm[c + 1] + sbt[c + 1];
            h[t][0] = 0.5f * g00 * (1.f + erff(g00 * 0.7071067811865476f));
            h[t][1] = 0.5f * g01 * (1.f + erff(g01 * 0.7071067811865476f));
            h[t][2] = 0.5f * g10 * (1.f + erff(g10 * 0.7071067811865476f));
            h[t][3] = 0.5f * g11 * (1.f + erff(g11 * 0.7071067811865476f));
        }

        // ---- GEMM2: m = g @ W2 (quad-shuffle remap, uint4 B reads) ----
        float m[8][4];
#pragma unroll
        for (int t = 0; t < 8; t++)
            m[t][0] = m[t][1] = m[t][2] = m[t][3] = 0.f;

        const int srcA = (lane & ~3) | (q >> 1);
        const int srcB = srcA + 2;
#pragma unroll
        for (int s = 0; s < 8; s++) {
            float t00 = __shfl_sync(FULL, h[s][0], srcA);
            float t01 = __shfl_sync(FULL, h[s][1], srcA);
            float t10 = __shfl_sync(FULL, h[s][2], srcA);
            float t11 = __shfl_sync(FULL, h[s][3], srcA);
            float u00 = __shfl_sync(FULL, h[s][0], srcB);
            float u01 = __shfl_sync(FULL, h[s][1], srcB);
            float u10 = __shfl_sync(FULL, h[s][2], srcB);
            float u11 = __shfl_sync(FULL, h[s][3], srcB);
            unsigned a0 = f2tf32((q & 1) ? t01 : t00);
            unsigned a1 = f2tf32((q & 1) ? t11 : t10);
            unsigned a2 = f2tf32((q & 1) ? u01 : u00);
            unsigned a3 = f2tf32((q & 1) ? u11 : u10);
#pragma unroll
            for (int tp = 0; tp < 4; tp++) {
                uint4 b = sW2q[(s * 4 + tp) * 32 + lane];
                mma_tf32(m[2 * tp],     a0, a1, a2, a3, b.x, b.y);
                mma_tf32(m[2 * tp + 1], a0, a1, a2, a3, b.z, b.w);
            }
        }

        // ---- v4 scatter-add ----
#pragma unroll
        for (int t = 0; t < 8; t++) {
            int c = 8 * t + 2 * q;
            float p0 = m[t][0] + sb2[c], p1 = m[t][1] + sb2[c + 1];
            float e0 = __shfl_xor_sync(FULL, p0, 1);
            float e1 = __shfl_xor_sync(FULL, p1, 1);
            float q2 = m[t][2] + sb2[c], q3 = m[t][3] + sb2[c + 1];
            float e2 = __shfl_xor_sync(FULL, q2, 1);
            float e3 = __shfl_xor_sync(FULL, q3, 1);
            if ((q & 1) == 0) {
                if (v0) {
                    float* dst = out + (size_t)j0 * CH + 8 * t + 2 * q;
                    asm volatile("red.global.add.v4.f32 [%0], {%1,%2,%3,%4};"
                                 :: "l"(dst), "f"(p0), "f"(p1), "f"(e0), "f"(e1)
                                 : "memory");
                }
            } else {
                if (v1) {
                    float* dst = out + (size_t)j1 * CH + 8 * t + 2 * (q - 1);
                    asm volatile("red.global.add.v4.f32 [%0], {%1,%2,%3,%4};"
                                 :: "l"(dst), "f"(e2), "f"(e3), "f"(q2), "f"(q3)
                                 : "memory");
                }
            }
        }
    }
}

// ---------------------------------------------------------------------------
extern "C" void kernel_launch(void* const* d_in, const int* in_sizes, int n_in,
                              void* d_out, int out_size) {
    const float* x     = (const float*)d_in[0];
    const void*  ei    = d_in[1];
    const float* ea    = (const float*)d_in[2];
    const float* W1    = (const float*)d_in[3];
    const float* b1    = (const float*)d_in[4];
    const float* gamma = (const float*)d_in[5];
    const float* beta  = (const float*)d_in[6];
    const float* W2    = (const float*)d_in[7];
    const float* b2    = (const float*)d_in[8];
    float* out = (float*)d_out;

    int n_nodes = in_sizes[0] / CH;
    int n_edges = in_sizes[2] / 32;

    detect_kernel<<<1, 32>>>((const unsigned*)ei);

    int n4 = out_size / 4;
    zero_kernel<<<(n4 + 255) / 256, 256>>>((float4*)out, n4);

    int n_node_tiles = (n_nodes + 15) / 16;
    node_precompute<<<(n_node_tiles + 7) / 8, 256>>>(x, W1, n_nodes);

    edge_kernel<<<NBLK, 256>>>(ei, ea, W1, b1, gamma, beta, W2, b2, out, n_edges);
}